// round 1
// baseline (speedup 1.0000x reference)
#include <cuda_runtime.h>
#include <math.h>

#define Bn 2
#define Sn 2048
#define Cn 1024
#define Hn 16
#define Dn 64
#define Mn (Bn*Sn)

// Scratch in [B,H,S,D] layout (16MB each) — __device__ globals, no allocation.
__device__ float g_q[Bn*Hn*Sn*Dn];
__device__ float g_k[Bn*Hn*Sn*Dn];
__device__ float g_v[Bn*Hn*Sn*Dn];

// ---------------------------------------------------------------------------
// Projection GEMM: A[M,K] @ W[K,N] + bias, scatter to q/k (MODE 0) or v (MODE 1)
// 128x128 tile, BK=8, 256 threads, 8x8 register tile per thread.
// ---------------------------------------------------------------------------
template<int MODE>
__global__ __launch_bounds__(256) void proj_kernel(const float* __restrict__ A,
                                                   const float* __restrict__ W,
                                                   const float* __restrict__ bias,
                                                   int N) {
    __shared__ float As[8][128];   // transposed A tile: As[k][m]
    __shared__ float Bs[8][128];   // Bs[k][n]
    const int K = Cn;
    const int bm = blockIdx.y * 128;
    const int bn = blockIdx.x * 128;
    const int tid = threadIdx.x;

    const int arow = tid >> 1, acol = (tid & 1) << 2;   // A: 128 rows x 8 cols via float4
    const int brow = tid >> 5, bcol = (tid & 31) << 2;  // W: 8 rows x 128 cols via float4
    const int tr = (tid >> 4) << 3;                     // thread row base in tile
    const int tc = (tid & 15) << 3;                     // thread col base in tile

    float acc[8][8];
    #pragma unroll
    for (int i = 0; i < 8; i++)
        #pragma unroll
        for (int j = 0; j < 8; j++) acc[i][j] = 0.f;

    const float* Aptr = A + (size_t)(bm + arow) * K + acol;
    const float* Wptr = W + (size_t)brow * N + bn + bcol;

    for (int k0 = 0; k0 < K; k0 += 8) {
        float4 a4 = *(const float4*)(Aptr + k0);
        As[acol + 0][arow] = a4.x;
        As[acol + 1][arow] = a4.y;
        As[acol + 2][arow] = a4.z;
        As[acol + 3][arow] = a4.w;
        *(float4*)&Bs[brow][bcol] = *(const float4*)(Wptr + (size_t)k0 * N);
        __syncthreads();

        #pragma unroll
        for (int kk = 0; kk < 8; kk++) {
            float4 a0 = *(float4*)&As[kk][tr];
            float4 a1 = *(float4*)&As[kk][tr + 4];
            float4 b0 = *(float4*)&Bs[kk][tc];
            float4 b1 = *(float4*)&Bs[kk][tc + 4];
            float av[8] = {a0.x, a0.y, a0.z, a0.w, a1.x, a1.y, a1.z, a1.w};
            float bw[8] = {b0.x, b0.y, b0.z, b0.w, b1.x, b1.y, b1.z, b1.w};
            #pragma unroll
            for (int i = 0; i < 8; i++)
                #pragma unroll
                for (int j = 0; j < 8; j++)
                    acc[i][j] += av[i] * bw[j];
        }
        __syncthreads();
    }

    // Epilogue: add bias, scatter into [B,H,S,D] layout.
    #pragma unroll
    for (int i = 0; i < 8; i++) {
        int m  = bm + tr + i;
        int bb = m / Sn;
        int s  = m - bb * Sn;
        #pragma unroll
        for (int j = 0; j < 8; j++) {
            int n = bn + tc + j;
            float val = acc[i][j] + bias[n];
            if (MODE == 0) {
                if (n < Cn) {
                    int h = n >> 6, d = n & 63;
                    g_q[(((size_t)bb * Hn + h) * Sn + s) * Dn + d] = val;
                } else {
                    int n2 = n - Cn;
                    int h = n2 >> 6, d = n2 & 63;
                    g_k[(((size_t)bb * Hn + h) * Sn + s) * Dn + d] = val;
                }
            } else {
                int h = n >> 6, d = n & 63;
                g_v[(((size_t)bb * Hn + h) * Sn + s) * Dn + d] = val;
            }
        }
    }
}

// ---------------------------------------------------------------------------
// Flash attention, fp32. Block = (bh, 64-row q-tile). 8 warps, 8 rows/warp.
// Lane owns output columns {lane, lane+32}. Online softmax is warp-local.
// ---------------------------------------------------------------------------
#define STR 68                         // smem row stride (floats): pad vs. bank conflicts
#define ATTN_SMEM (4 * 64 * STR * 4)   // Qs + Ks + Vs + Ps

__global__ __launch_bounds__(256) void attn_kernel(float* __restrict__ out) {
    extern __shared__ float sm[];
    float* Qs = sm;
    float* Ks = Qs + 64 * STR;
    float* Vs = Ks + 64 * STR;
    float* Ps = Vs + 64 * STR;

    const int bh = blockIdx.y;          // 0..31
    const int b  = bh >> 4;
    const int h  = bh & 15;
    const int qtile = blockIdx.x;       // 0..31
    const int tid  = threadIdx.x;
    const int warp = tid >> 5;
    const int lane = tid & 31;
    const int r0   = warp << 3;         // first q-row of this warp (tile-local)

    const float* qbase = g_q + ((size_t)bh * Sn + (size_t)qtile * 64) * Dn;
    const float* kbase = g_k + (size_t)bh * Sn * Dn;
    const float* vbase = g_v + (size_t)bh * Sn * Dn;

    // Load Q tile (64x64 floats) once.
    #pragma unroll
    for (int it = 0; it < 4; it++) {
        int f4  = tid + it * 256;       // float4 index 0..1023
        int row = f4 >> 4;
        int col = (f4 & 15) << 2;
        *(float4*)&Qs[row * STR + col] = *(const float4*)(qbase + row * 64 + col);
    }

    float m_r[8], l_r[8], o0[8], o1[8];
    #pragma unroll
    for (int r = 0; r < 8; r++) { m_r[r] = -INFINITY; l_r[r] = 0.f; o0[r] = 0.f; o1[r] = 0.f; }

    const float scale = 0.125f;   // 1/sqrt(Dv), Dv = 64

    for (int kt = 0; kt <= qtile; kt++) {
        __syncthreads();   // previous-iteration smem readers done
        #pragma unroll
        for (int it = 0; it < 4; it++) {
            int f4  = tid + it * 256;
            int row = f4 >> 4;
            int col = (f4 & 15) << 2;
            *(float4*)&Ks[row * STR + col] = *(const float4*)(kbase + (size_t)(kt * 64 + row) * 64 + col);
            *(float4*)&Vs[row * STR + col] = *(const float4*)(vbase + (size_t)(kt * 64 + row) * 64 + col);
        }
        __syncthreads();

        // S = Q K^T for this warp's 8 rows x 64 cols (lane cols: lane, lane+32)
        float s0[8], s1[8];
        #pragma unroll
        for (int r = 0; r < 8; r++) { s0[r] = 0.f; s1[r] = 0.f; }
        #pragma unroll
        for (int d4 = 0; d4 < 16; d4++) {
            float4 k0 = *(float4*)&Ks[lane * STR + d4 * 4];
            float4 k1 = *(float4*)&Ks[(lane + 32) * STR + d4 * 4];
            #pragma unroll
            for (int r = 0; r < 8; r++) {
                float4 q = *(float4*)&Qs[(r0 + r) * STR + d4 * 4];
                s0[r] += q.x * k0.x + q.y * k0.y + q.z * k0.z + q.w * k0.w;
                s1[r] += q.x * k1.x + q.y * k1.y + q.z * k1.z + q.w * k1.w;
            }
        }

        const bool diag = (kt == qtile);
        #pragma unroll
        for (int r = 0; r < 8; r++) {
            float a = s0[r] * scale;
            float c = s1[r] * scale;
            if (diag) {
                int qg = r0 + r;     // tile-local indices are valid on the diagonal tile
                if (lane > qg)      a = -1e30f;
                if (lane + 32 > qg) c = -1e30f;
            }
            float mx = fmaxf(a, c);
            #pragma unroll
            for (int off = 16; off; off >>= 1)
                mx = fmaxf(mx, __shfl_xor_sync(0xffffffffu, mx, off));
            float mnew = fmaxf(m_r[r], mx);
            float corr = __expf(m_r[r] - mnew);
            float p0 = __expf(a - mnew);
            float p1 = __expf(c - mnew);
            float ps = p0 + p1;
            #pragma unroll
            for (int off = 16; off; off >>= 1)
                ps += __shfl_xor_sync(0xffffffffu, ps, off);
            l_r[r] = l_r[r] * corr + ps;
            m_r[r] = mnew;
            o0[r] *= corr;
            o1[r] *= corr;
            Ps[(r0 + r) * STR + lane]      = p0;
            Ps[(r0 + r) * STR + lane + 32] = p1;
        }
        __syncwarp();

        // O += P @ V   (lane's output cols: lane, lane+32)
        #pragma unroll
        for (int j4 = 0; j4 < 16; j4++) {
            float v00 = Vs[(j4 * 4 + 0) * STR + lane];
            float v01 = Vs[(j4 * 4 + 1) * STR + lane];
            float v02 = Vs[(j4 * 4 + 2) * STR + lane];
            float v03 = Vs[(j4 * 4 + 3) * STR + lane];
            float v10 = Vs[(j4 * 4 + 0) * STR + lane + 32];
            float v11 = Vs[(j4 * 4 + 1) * STR + lane + 32];
            float v12 = Vs[(j4 * 4 + 2) * STR + lane + 32];
            float v13 = Vs[(j4 * 4 + 3) * STR + lane + 32];
            #pragma unroll
            for (int r = 0; r < 8; r++) {
                float4 p = *(float4*)&Ps[(r0 + r) * STR + j4 * 4];
                o0[r] += p.x * v00 + p.y * v01 + p.z * v02 + p.w * v03;
                o1[r] += p.x * v10 + p.y * v11 + p.z * v12 + p.w * v13;
            }
        }
    }

    // Epilogue: normalize, write out[b][s][h*64 + dv]
    #pragma unroll
    for (int r = 0; r < 8; r++) {
        float inv = 1.f / l_r[r];
        int sg = qtile * 64 + r0 + r;
        float* op = out + ((size_t)b * Sn + sg) * Cn + h * 64;
        op[lane]      = o0[r] * inv;
        op[lane + 32] = o1[r] * inv;
    }
}

// ---------------------------------------------------------------------------
extern "C" void kernel_launch(void* const* d_in, const int* in_sizes, int n_in,
                              void* d_out, int out_size) {
    const float* x   = (const float*)d_in[0];
    const float* Wqk = (const float*)d_in[1];
    const float* bqk = (const float*)d_in[2];
    const float* Wv  = (const float*)d_in[3];
    const float* bv  = (const float*)d_in[4];
    float* out = (float*)d_out;

    // QK projection: N = 2048
    {
        dim3 grid(2048 / 128, Mn / 128);
        proj_kernel<0><<<grid, 256>>>(x, Wqk, bqk, 2048);
    }
    // V projection: N = 1024
    {
        dim3 grid(1024 / 128, Mn / 128);
        proj_kernel<1><<<grid, 256>>>(x, Wv, bv, 1024);
    }
    // Attention: grid (q-tiles, B*H)
    {
        cudaFuncSetAttribute(attn_kernel, cudaFuncAttributeMaxDynamicSharedMemorySize, ATTN_SMEM);
        dim3 grid(Sn / 64, Bn * Hn);
        attn_kernel<<<grid, 256, ATTN_SMEM>>>(out);
    }
}